// round 15
// baseline (speedup 1.0000x reference)
#include <cuda_runtime.h>
#include <math.h>

#define BSZ 64
#define TT  512
#define DA  16
#define DZ  32
#define KK  3
#define GG  12   // 4*H, H=3

// ---------------- scratch (device globals; no allocs allowed) ----------------
__device__ float g_xw0[(size_t)BSZ * TT * GG];
__device__ float g_alpha[(size_t)BSZ * TT * KK];
__device__ float g_muf[(size_t)TT * BSZ * DZ];
__device__ float g_mup[(size_t)TT * BSZ * DZ];
__device__ float g_sigf[(size_t)TT * BSZ * DZ * DZ];   // 128 MiB
__device__ float g_sigp[(size_t)TT * BSZ * DZ * DZ];   // 128 MiB
__device__ float g_pinv[(size_t)TT * BSZ * DZ * DZ];   // 128 MiB (sigp^-1)

__device__ __forceinline__ float fsigm(float x) {
    return __fdividef(1.0f, 1.0f + __expf(-x));
}
__device__ __forceinline__ float ftanh(float x) {
    x = fminf(fmaxf(x, -10.0f), 10.0f);
    float e = __expf(2.0f * x);
    return __fdividef(e - 1.0f, e + 1.0f);
}

// ---- register/shuffle Gauss-Jordan on smem, row-per-lane, deferred scaling ----
template <int N, int LD>
__device__ __forceinline__ void warp_gj_reg(float* M, int lane) {
    const int i = (N == 32) ? lane : (lane & (N - 1));
    float c[N];
#pragma unroll
    for (int j = 0; j < N; j++) c[j] = M[i * LD + j];
    float dinv = 1.0f;
#pragma unroll
    for (int p = 0; p < N; p++) {
        float pv = __shfl_sync(0xffffffffu, c[p], p);
        float rpv = __fdividef(1.0f, pv);
        float f = (i == p) ? 0.0f : c[p] * rpv;
        if (i == p) dinv = rpv;
        float ncp = (i == p) ? 1.0f : -f;
#pragma unroll
        for (int j = 0; j < N; j++)
            if (j != p) c[j] -= f * __shfl_sync(0xffffffffu, c[j], p);
        c[p] = ncp;
    }
    if (lane < N) {
#pragma unroll
        for (int j = 0; j < N; j++) M[i * LD + j] = c[j] * dinv;
    }
    __syncwarp();
}

// ---------------- Kernel A0: input projection for LSTM layer 0 ----------------
__global__ void xw0_kernel(const float* __restrict__ a,
                           const float* __restrict__ Wih0,
                           const float* __restrict__ bih0,
                           const float* __restrict__ bhh0) {
    int idx = blockIdx.x * blockDim.x + threadIdx.x;
    if (idx >= BSZ * TT * GG) return;
    int j  = idx % GG;
    int bt = idx / GG;
    const float* ar = a + (size_t)bt * DA;
    const float* w  = Wih0 + j * DA;
    float s = bih0[j] + bhh0[j];
#pragma unroll
    for (int d = 0; d < DA; d++) s += ar[d] * w[d];
    g_xw0[idx] = s;
}

// ---------------- Kernel A1: sequential 2-layer LSTM + softmax ----------------
__global__ void lstm_kernel(const float* __restrict__ Whh0,
                            const float* __restrict__ Wih1,
                            const float* __restrict__ Whh1,
                            const float* __restrict__ bih1,
                            const float* __restrict__ bhh1) {
    __shared__ float whh0[GG][3], wih1[GG][3], whh1[GG][3], b1[GG];
    int tid = threadIdx.x;
    if (tid < 36) {
        whh0[tid / 3][tid % 3] = Whh0[tid];
        wih1[tid / 3][tid % 3] = Wih1[tid];
        whh1[tid / 3][tid % 3] = Whh1[tid];
    }
    if (tid < GG) b1[tid] = bih1[tid] + bhh1[tid];
    __syncthreads();

    int b = tid;
    if (b >= BSZ) return;
    float h0[3] = {0, 0, 0}, c0[3] = {0, 0, 0};
    float h1[3] = {0, 0, 0}, c1[3] = {0, 0, 0};
    const float* xw = g_xw0 + (size_t)b * TT * GG;
    float* al = g_alpha + (size_t)b * TT * KK;

    for (int t = 0; t < TT; t++) {
        float g[GG];
#pragma unroll
        for (int j = 0; j < GG; j++)
            g[j] = xw[t * GG + j] + whh0[j][0] * h0[0] + whh0[j][1] * h0[1] + whh0[j][2] * h0[2];
#pragma unroll
        for (int u = 0; u < 3; u++) {
            c0[u] = fsigm(g[3 + u]) * c0[u] + fsigm(g[u]) * ftanh(g[6 + u]);
            h0[u] = fsigm(g[9 + u]) * ftanh(c0[u]);
        }
#pragma unroll
        for (int j = 0; j < GG; j++)
            g[j] = b1[j] + wih1[j][0] * h0[0] + wih1[j][1] * h0[1] + wih1[j][2] * h0[2]
                         + whh1[j][0] * h1[0] + whh1[j][1] * h1[1] + whh1[j][2] * h1[2];
#pragma unroll
        for (int u = 0; u < 3; u++) {
            c1[u] = fsigm(g[3 + u]) * c1[u] + fsigm(g[u]) * ftanh(g[6 + u]);
            h1[u] = fsigm(g[9 + u]) * ftanh(c1[u]);
        }
        float m = fmaxf(h1[0], fmaxf(h1[1], h1[2]));
        float e0 = __expf(h1[0] - m), e1 = __expf(h1[1] - m), e2 = __expf(h1[2] - m);
        float inv = __fdividef(1.0f, e0 + e1 + e2);
        al[t * KK + 0] = e0 * inv;
        al[t * KK + 1] = e1 * inv;
        al[t * KK + 2] = e2 * inv;
    }
}

// ---------------- Kernel B: forward Kalman filter ----------------
// Double-buffered mixed At/Ct. Per step (4 barriers):
//   P1 r,M1,M1T | P2 S,WT,HT,w | P3 GJ16 (warp0) | P45 prefetch->nxt + V,Kg,G + updates
__global__ void __launch_bounds__(256) fwd_kernel(const float* __restrict__ a,
                                                  const float* __restrict__ A,
                                                  const float* __restrict__ C,
                                                  const float* __restrict__ R,
                                                  const float* __restrict__ Q,
                                                  const float* __restrict__ mu0,
                                                  const float* __restrict__ sigma0) {
    const int b = blockIdx.x;
    const int tid = threadIdx.x;
    const int i8 = tid >> 3;
    const int q4 = (tid & 7) * 4;
    const int jj = (tid & 7) * 2;

    __shared__ __align__(16) float sAt[2][DZ][36];
    __shared__ __align__(16) float sCt[2][DA][36];
    __shared__ __align__(16) float sCtT[2][DZ][20];
    __shared__ __align__(16) float sSigP[DZ][36], sQ[DZ][36];
    __shared__ __align__(16) float sWT[DZ][36];
    __shared__ __align__(16) float sM1[DZ][20], sKg[DZ][20], sG[DZ][20];
    __shared__ __align__(16) float sM1T[DA][36], sHT[DA][36];
    __shared__ __align__(16) float sS[DA][20];
    __shared__ float sR[DA][17];
    __shared__ float smu_f[DZ], smu_p[DZ], sw[DZ], sr[DA];

    float pa = 0.f;  // prefetched a[b][t][tid] for tid<16

    if (tid < DZ) { smu_f[tid] = mu0[tid]; smu_p[tid] = mu0[tid]; }
    {
        int e = tid * 4, ii = e >> 5, jc = e & 31;
        *(float4*)&sSigP[ii][jc] = ((const float4*)sigma0)[tid];
        *(float4*)&sQ[ii][jc]    = ((const float4*)Q)[tid];
        sR[tid >> 4][tid & 15] = R[tid];
    }
    // prologue: mix t=0 into buffer 0
    {
        const size_t ab = (size_t)b * TT * KK;
        const float a0 = g_alpha[ab + 0], a1 = g_alpha[ab + 1], a2 = g_alpha[ab + 2];
        const float4* A0 = (const float4*)A;
        const float4* A1 = A0 + (size_t)TT * 256;
        const float4* A2 = A1 + (size_t)TT * 256;
        float4 v0 = A0[tid], v1 = A1[tid], v2 = A2[tid], m;
        m.x = a0 * v0.x + a1 * v1.x + a2 * v2.x;
        m.y = a0 * v0.y + a1 * v1.y + a2 * v2.y;
        m.z = a0 * v0.z + a1 * v1.z + a2 * v2.z;
        m.w = a0 * v0.w + a1 * v1.w + a2 * v2.w;
        int e = tid * 4, ii = e >> 5, jc = e & 31;
        *(float4*)&sAt[0][ii][jc] = m;
        if (tid < 128) {
            const float4* C0 = (const float4*)C;
            const float4* C1 = C0 + (size_t)TT * 128;
            const float4* C2 = C1 + (size_t)TT * 128;
            float4 w0 = C0[tid], w1 = C1[tid], w2 = C2[tid], c;
            c.x = a0 * w0.x + a1 * w1.x + a2 * w2.x;
            c.y = a0 * w0.y + a1 * w1.y + a2 * w2.y;
            c.z = a0 * w0.z + a1 * w1.z + a2 * w2.z;
            c.w = a0 * w0.w + a1 * w1.w + a2 * w2.w;
            int ec = tid * 4, ic = ec >> 5, jcc = ec & 31;
            *(float4*)&sCt[0][ic][jcc] = c;
            sCtT[0][jcc + 0][ic] = c.x; sCtT[0][jcc + 1][ic] = c.y;
            sCtT[0][jcc + 2][ic] = c.z; sCtT[0][jcc + 3][ic] = c.w;
        }
        if (tid < DA) pa = a[(size_t)b * TT * DA + tid];
    }
    __syncthreads();

    for (int t = 0; t < TT; t++) {
        const int cur = t & 1, nxt = cur ^ 1;

        // P1: r = a - Ct mu_f ; M1 = sigP * CtT (+ M1T)
        if (tid < DA) {
            float s = pa;
#pragma unroll
            for (int j = 0; j < DZ; j++) s -= sCt[cur][tid][j] * smu_f[j];
            sr[tid] = s;
        }
        {
            float s0 = 0.f, s1 = 0.f;
#pragma unroll
            for (int k = 0; k < DZ; k++) {
                float av = sSigP[i8][k];
                s0 += av * sCtT[cur][k][jj];
                s1 += av * sCtT[cur][k][jj + 1];
            }
            sM1[i8][jj] = s0; sM1[i8][jj + 1] = s1;
            sM1T[jj][i8] = s0; sM1T[jj + 1][i8] = s1;
        }
        __syncthreads();

        // P2: S = Ct*M1 + R ; WT = (At*sigP)^T ; HT = (At*M1)^T ; w = At*mu_p
        {
            {
                int i = tid >> 4, j = tid & 15;
                float s = sR[i][j];
#pragma unroll
                for (int k = 0; k < DZ; k++) s += sCt[cur][i][k] * sM1[k][j];
                sS[i][j] = s;
            }
            {
                float4 acc = make_float4(0, 0, 0, 0);
#pragma unroll
                for (int k = 0; k < DZ; k++) {
                    float av = sAt[cur][i8][k];
                    float4 bv = *(const float4*)&sSigP[k][q4];
                    acc.x += av * bv.x; acc.y += av * bv.y;
                    acc.z += av * bv.z; acc.w += av * bv.w;
                }
                sWT[q4 + 0][i8] = acc.x; sWT[q4 + 1][i8] = acc.y;
                sWT[q4 + 2][i8] = acc.z; sWT[q4 + 3][i8] = acc.w;
            }
#pragma unroll
            for (int rep = 0; rep < 2; rep++) {
                int u = tid + rep * 256;
                int i = u >> 4, j = u & 15;
                float h = 0.f;
#pragma unroll
                for (int k = 0; k < DZ; k++) h += sAt[cur][i][k] * sM1[k][j];
                sHT[j][i] = h;
            }
            if (tid < DZ) {
                float s = 0.f;
#pragma unroll
                for (int k = 0; k < DZ; k++) s += sAt[cur][tid][k] * smu_p[k];
                sw[tid] = s;
            }
        }
        __syncthreads();

        // P3: warp 0 inverts S in place (serial)
        if (tid < 32) warp_gj_reg<DA, 20>(&sS[0][0], tid);
        __syncthreads();

        // P45: prefetch t+1 mix into buffer nxt ; V,Kg,G ; updates (intra-warp)
        {
            if (t + 1 < TT) {
                const size_t ab2 = ((size_t)b * TT + (t + 1)) * KK;
                const float na0 = g_alpha[ab2 + 0];
                const float na1 = g_alpha[ab2 + 1];
                const float na2 = g_alpha[ab2 + 2];
                const float4* A0 = (const float4*)A + (size_t)(t + 1) * 256;
                const float4* A1 = A0 + (size_t)TT * 256;
                const float4* A2 = A1 + (size_t)TT * 256;
                float4 v0 = A0[tid], v1 = A1[tid], v2 = A2[tid], m;
                m.x = na0 * v0.x + na1 * v1.x + na2 * v2.x;
                m.y = na0 * v0.y + na1 * v1.y + na2 * v2.y;
                m.z = na0 * v0.z + na1 * v1.z + na2 * v2.z;
                m.w = na0 * v0.w + na1 * v1.w + na2 * v2.w;
                int e = tid * 4, ii = e >> 5, jc = e & 31;
                *(float4*)&sAt[nxt][ii][jc] = m;
                if (tid < 128) {
                    const float4* C0 = (const float4*)C + (size_t)(t + 1) * 128;
                    const float4* C1 = C0 + (size_t)TT * 128;
                    const float4* C2 = C1 + (size_t)TT * 128;
                    float4 w0 = C0[tid], w1 = C1[tid], w2 = C2[tid], c;
                    c.x = na0 * w0.x + na1 * w1.x + na2 * w2.x;
                    c.y = na0 * w0.y + na1 * w1.y + na2 * w2.y;
                    c.z = na0 * w0.z + na1 * w1.z + na2 * w2.z;
                    c.w = na0 * w0.w + na1 * w1.w + na2 * w2.w;
                    int ec = tid * 4, ic = ec >> 5, jcc = ec & 31;
                    *(float4*)&sCt[nxt][ic][jcc] = c;
                    sCtT[nxt][jcc + 0][ic] = c.x; sCtT[nxt][jcc + 1][ic] = c.y;
                    sCtT[nxt][jcc + 2][ic] = c.z; sCtT[nxt][jcc + 3][ic] = c.w;
                }
                if (tid < DA) pa = a[((size_t)b * TT + (t + 1)) * DA + tid];
            }

            // Kg, G rows (intra-warp)
            float k0 = 0.f, k1 = 0.f, g0 = 0.f, g1 = 0.f;
#pragma unroll
            for (int k = 0; k < DA; k++) {
                float m = sM1[i8][k];
                float h = sHT[k][i8];
                float s0 = sS[k][jj], s1 = sS[k][jj + 1];
                k0 += m * s0; k1 += m * s1;
                g0 += h * s0; g1 += h * s1;
            }
            sKg[i8][jj] = k0; sKg[i8][jj + 1] = k1;
            sG[i8][jj]  = g0; sG[i8][jj + 1]  = g1;
            __syncwarp();

            const size_t sb = (size_t)t * BSZ + b;

            float4 accN = *(const float4*)&sSigP[i8][q4];
            float4 accP = *(const float4*)&sQ[i8][q4];
#pragma unroll
            for (int k = 0; k < DZ; k++) {
                float av = sAt[cur][i8][k];
                float4 bv = *(const float4*)&sWT[k][q4];
                accP.x += av * bv.x; accP.y += av * bv.y;
                accP.z += av * bv.z; accP.w += av * bv.w;
            }
#pragma unroll
            for (int k = 0; k < DA; k++) {
                float kg = sKg[i8][k];
                float gg = sG[i8][k];
                float4 m = *(const float4*)&sM1T[k][q4];
                float4 h = *(const float4*)&sHT[k][q4];
                accN.x -= kg * m.x; accN.y -= kg * m.y;
                accN.z -= kg * m.z; accN.w -= kg * m.w;
                accP.x -= gg * h.x; accP.y -= gg * h.y;
                accP.z -= gg * h.z; accP.w -= gg * h.w;
            }
            *(float4*)&g_sigf[sb * (DZ * DZ) + i8 * DZ + q4] = accN;
            *(float4*)&sSigP[i8][q4] = accP;
            *(float4*)&g_sigp[sb * (DZ * DZ) + i8 * DZ + q4] = accP;

            float pm = k0 * sr[jj] + k1 * sr[jj + 1];
            float pg = g0 * sr[jj] + g1 * sr[jj + 1];
#pragma unroll
            for (int o = 4; o >= 1; o >>= 1) {
                pm += __shfl_down_sync(0xffffffffu, pm, o);
                pg += __shfl_down_sync(0xffffffffu, pg, o);
            }
            if ((tid & 7) == 0) {
                float mn = smu_p[i8] + pm;
                float mp = sw[i8] + pg;
                smu_f[i8] = mn; g_muf[sb * DZ + i8] = mn;
                smu_p[i8] = mp; g_mup[sb * DZ + i8] = mp;
            }
        }
        __syncthreads();
    }
}

// ---------------- Kernel I: batch-parallel inversion of all sigp_t ----------
__global__ void __launch_bounds__(256) inv_kernel() {
    const int w = blockIdx.x * (blockDim.x >> 5) + (threadIdx.x >> 5);
    if (w >= TT * BSZ) return;
    const int lane = threadIdx.x & 31;

    const float4* src = (const float4*)(g_sigp + (size_t)w * (DZ * DZ));
    float c[DZ];
#pragma unroll
    for (int s = 0; s < 8; s++) {
        float4 v = src[lane * 8 + s];
        c[s * 4 + 0] = v.x; c[s * 4 + 1] = v.y;
        c[s * 4 + 2] = v.z; c[s * 4 + 3] = v.w;
    }
    float dinv = 1.0f;
#pragma unroll
    for (int p = 0; p < DZ; p++) {
        float pv = __shfl_sync(0xffffffffu, c[p], p);
        float rpv = __fdividef(1.0f, pv);
        float f = (lane == p) ? 0.0f : c[p] * rpv;
        if (lane == p) dinv = rpv;
        float ncp = (lane == p) ? 1.0f : -f;
#pragma unroll
        for (int j = 0; j < DZ; j++)
            if (j != p) c[j] -= f * __shfl_sync(0xffffffffu, c[j], p);
        c[p] = ncp;
    }
    float4* dst = (float4*)(g_pinv + (size_t)w * (DZ * DZ));
#pragma unroll
    for (int s = 0; s < 8; s++) {
        float4 v;
        v.x = c[s * 4 + 0] * dinv; v.y = c[s * 4 + 1] * dinv;
        v.z = c[s * 4 + 2] * dinv; v.w = c[s * 4 + 3] * dinv;
        dst[lane * 8 + s] = v;
    }
}

// ---------------- Kernel C: RTS backward smoother (2 barriers/step) ----------
// P1 prefetch-issue + U,X,xv | P2 outputs + commit prefetched inputs.
__global__ void __launch_bounds__(256) bwd_kernel(const float* __restrict__ A,
                                                  float* __restrict__ out) {
    const int b = blockIdx.x;
    const int tid = threadIdx.x;
    const int i8 = tid >> 3;
    const int q4 = (tid & 7) * 4;

    __shared__ __align__(16) float sAT[DZ][36];
    __shared__ __align__(16) float sSigF[2][DZ][36];
    __shared__ __align__(16) float sSigNc[DZ][36], sD[DZ][36];
    __shared__ __align__(16) float sU[DZ][36], sX[DZ][36], sPinv[DZ][36];
    __shared__ float sMuN[DZ], sMuD[DZ], sxv[DZ];

    float4 pAT = make_float4(0, 0, 0, 0);
    float4 pSF = make_float4(0, 0, 0, 0);
    float4 pPI = make_float4(0, 0, 0, 0);
    float4 pSP = make_float4(0, 0, 0, 0);
    float pMUP = 0.f;

    // prologue: t = TT-1 outputs + carry ; load t = TT-2 inputs into buffers[0]
    {
        size_t sb = ((size_t)(TT - 1) * BSZ + b);
        size_t ob = ((size_t)b * TT + (TT - 1)) * (DZ + DZ * DZ);
        int e = tid * 4, ii = e >> 5, jj = e & 31;
        float4 v = ((const float4*)(g_sigf + sb * (DZ * DZ)))[tid];
        *(float4*)&sSigNc[ii][jj] = v;
        *(float4*)&out[ob + DZ + e] = v;
        if (tid < DZ) {
            float m = g_muf[sb * DZ + tid];
            sMuN[tid] = m;
            out[ob + tid] = m;
        }
        const int t0 = TT - 2;
        const size_t sb2 = (size_t)t0 * BSZ + b;
        const size_t ab = ((size_t)b * TT + (t0 + 1)) * KK;
        const float a0 = g_alpha[ab + 0], a1 = g_alpha[ab + 1], a2 = g_alpha[ab + 2];
        const float4* A0 = (const float4*)A + (size_t)(t0 + 1) * 256;
        const float4* A1 = A0 + (size_t)TT * 256;
        const float4* A2 = A1 + (size_t)TT * 256;
        float4 v0 = A0[tid], v1 = A1[tid], v2 = A2[tid];
        sAT[jj + 0][ii] = a0 * v0.x + a1 * v1.x + a2 * v2.x;
        sAT[jj + 1][ii] = a0 * v0.y + a1 * v1.y + a2 * v2.y;
        sAT[jj + 2][ii] = a0 * v0.z + a1 * v1.z + a2 * v2.z;
        sAT[jj + 3][ii] = a0 * v0.w + a1 * v1.w + a2 * v2.w;
        *(float4*)&sSigF[0][ii][jj] = ((const float4*)(g_sigf + sb2 * (DZ * DZ)))[tid];
        *(float4*)&sPinv[ii][jj] = ((const float4*)(g_pinv + sb2 * (DZ * DZ)))[tid];
        float4 sp = ((const float4*)(g_sigp + sb2 * (DZ * DZ)))[tid];
        float4 n = make_float4(sSigNc[ii][jj + 0], sSigNc[ii][jj + 1],
                               sSigNc[ii][jj + 2], sSigNc[ii][jj + 3]);
        float4 d = make_float4(n.x - sp.x, n.y - sp.y, n.z - sp.z, n.w - sp.w);
        *(float4*)&sD[ii][jj] = d;
        if (tid < DZ) sMuD[tid] = sMuN[tid] - g_mup[sb2 * DZ + tid];
    }
    __syncthreads();

    for (int t = TT - 2; t >= 0; t--) {
        const int cur = (TT - 2 - t) & 1, nxt = cur ^ 1;
        const size_t sb = (size_t)t * BSZ + b;

        // P1: issue prefetch for t-1 ; compute U = sigF*AT, X = Pinv*D, xv
        if (t > 0) {
            const int t2 = t - 1;
            const size_t sb2 = (size_t)t2 * BSZ + b;
            const size_t ab2 = ((size_t)b * TT + (t2 + 1)) * KK;
            const float na0 = g_alpha[ab2 + 0];
            const float na1 = g_alpha[ab2 + 1];
            const float na2 = g_alpha[ab2 + 2];
            const float4* A0 = (const float4*)A + (size_t)(t2 + 1) * 256;
            const float4* A1 = A0 + (size_t)TT * 256;
            const float4* A2 = A1 + (size_t)TT * 256;
            float4 v0 = A0[tid], v1 = A1[tid], v2 = A2[tid];
            pAT.x = na0 * v0.x + na1 * v1.x + na2 * v2.x;
            pAT.y = na0 * v0.y + na1 * v1.y + na2 * v2.y;
            pAT.z = na0 * v0.z + na1 * v1.z + na2 * v2.z;
            pAT.w = na0 * v0.w + na1 * v1.w + na2 * v2.w;
            pSF = ((const float4*)(g_sigf + sb2 * (DZ * DZ)))[tid];
            pPI = ((const float4*)(g_pinv + sb2 * (DZ * DZ)))[tid];
            pSP = ((const float4*)(g_sigp + sb2 * (DZ * DZ)))[tid];
            if (tid < DZ) pMUP = g_mup[sb2 * DZ + tid];
        }
        {
            float4 au = make_float4(0, 0, 0, 0);
            float4 ax = make_float4(0, 0, 0, 0);
#pragma unroll
            for (int k = 0; k < DZ; k++) {
                float fu = sSigF[cur][i8][k];
                float fx = sPinv[i8][k];
                float4 bu = *(const float4*)&sAT[k][q4];
                float4 bx = *(const float4*)&sD[k][q4];
                au.x += fu * bu.x; au.y += fu * bu.y;
                au.z += fu * bu.z; au.w += fu * bu.w;
                ax.x += fx * bx.x; ax.y += fx * bx.y;
                ax.z += fx * bx.z; ax.w += fx * bx.w;
            }
            *(float4*)&sU[i8][q4] = au;
            *(float4*)&sX[i8][q4] = ax;
            if (tid < DZ) {
                float s = 0.f;
#pragma unroll
                for (int k = 0; k < DZ; k++) s += sPinv[tid][k] * sMuD[k];
                sxv[tid] = s;
            }
        }
        __syncthreads();

        // P2: outputs + carry ; commit prefetched inputs (sAT/sPinv/sSigF[nxt]/sD/muD)
        {
            const size_t ob = ((size_t)b * TT + t) * (DZ + DZ * DZ);
            float4 acc = *(const float4*)&sSigF[cur][i8][q4];
#pragma unroll
            for (int k = 0; k < DZ; k++) {
                float av = sU[i8][k];
                float4 bv = *(const float4*)&sX[k][q4];
                acc.x += av * bv.x; acc.y += av * bv.y;
                acc.z += av * bv.z; acc.w += av * bv.w;
            }
            *(float4*)&sSigNc[i8][q4] = acc;
            *(float4*)&out[ob + DZ + i8 * DZ + q4] = acc;
            float muNew = 0.f;
            if (tid < DZ) {
                float s = g_muf[sb * DZ + tid];
#pragma unroll
                for (int k = 0; k < DZ; k++) s += sU[tid][k] * sxv[k];
                muNew = s;
                sMuN[tid] = s;
                out[ob + tid] = s;
            }
            if (t > 0) {
                int e = tid * 4, ii = e >> 5, jj = e & 31;
                sAT[jj + 0][ii] = pAT.x; sAT[jj + 1][ii] = pAT.y;
                sAT[jj + 2][ii] = pAT.z; sAT[jj + 3][ii] = pAT.w;
                *(float4*)&sSigF[nxt][ii][jj] = pSF;
                *(float4*)&sPinv[ii][jj] = pPI;
                // D for t-1 from just-computed sigNc (same thread: ii==i8, jj==q4)
                float4 d = make_float4(acc.x - pSP.x, acc.y - pSP.y,
                                       acc.z - pSP.z, acc.w - pSP.w);
                *(float4*)&sD[ii][jj] = d;
                if (tid < DZ) sMuD[tid] = muNew - pMUP;
            }
        }
        __syncthreads();
    }
}

// ---------------- launch ----------------
extern "C" void kernel_launch(void* const* d_in, const int* in_sizes, int n_in,
                              void* d_out, int out_size) {
    const float* a      = (const float*)d_in[0];
    const float* A      = (const float*)d_in[1];
    const float* C      = (const float*)d_in[2];
    const float* R      = (const float*)d_in[3];
    const float* Q      = (const float*)d_in[4];
    const float* mu0    = (const float*)d_in[5];
    const float* sigma0 = (const float*)d_in[6];
    const float* Wih0   = (const float*)d_in[7];
    const float* Whh0   = (const float*)d_in[8];
    const float* bih0   = (const float*)d_in[9];
    const float* bhh0   = (const float*)d_in[10];
    const float* Wih1   = (const float*)d_in[11];
    const float* Whh1   = (const float*)d_in[12];
    const float* bih1   = (const float*)d_in[13];
    const float* bhh1   = (const float*)d_in[14];
    float* out = (float*)d_out;

    int n0 = BSZ * TT * GG;
    xw0_kernel<<<(n0 + 255) / 256, 256>>>(a, Wih0, bih0, bhh0);
    lstm_kernel<<<1, 64>>>(Whh0, Wih1, Whh1, bih1, bhh1);
    fwd_kernel<<<BSZ, 256>>>(a, A, C, R, Q, mu0, sigma0);
    inv_kernel<<<(TT * BSZ) / 8, 256>>>();
    bwd_kernel<<<BSZ, 256>>>(A, out);
}

// round 16
// speedup vs baseline: 1.0425x; 1.0425x over previous
#include <cuda_runtime.h>
#include <math.h>

#define BSZ 64
#define TT  512
#define DA  16
#define DZ  32
#define KK  3
#define GG  12   // 4*H, H=3

// ---------------- scratch (device globals; no allocs allowed) ----------------
__device__ float g_xw0[(size_t)BSZ * TT * GG];
__device__ float g_alpha[(size_t)BSZ * TT * KK];
__device__ float g_muf[(size_t)TT * BSZ * DZ];
__device__ float g_mup[(size_t)TT * BSZ * DZ];
__device__ float g_sigf[(size_t)TT * BSZ * DZ * DZ];   // 128 MiB
__device__ float g_sigp[(size_t)TT * BSZ * DZ * DZ];   // 128 MiB
__device__ float g_pinv[(size_t)TT * BSZ * DZ * DZ];   // 128 MiB (sigp^-1)

__device__ __forceinline__ float fsigm(float x) {
    return __fdividef(1.0f, 1.0f + __expf(-x));
}
__device__ __forceinline__ float ftanh(float x) {
    x = fminf(fmaxf(x, -10.0f), 10.0f);
    float e = __expf(2.0f * x);
    return __fdividef(e - 1.0f, e + 1.0f);
}

// ---- register/shuffle Gauss-Jordan on smem, row-per-lane, deferred scaling ----
template <int N, int LD>
__device__ __forceinline__ void warp_gj_reg(float* M, int lane) {
    const int i = (N == 32) ? lane : (lane & (N - 1));
    float c[N];
#pragma unroll
    for (int j = 0; j < N; j++) c[j] = M[i * LD + j];
    float dinv = 1.0f;
#pragma unroll
    for (int p = 0; p < N; p++) {
        float pv = __shfl_sync(0xffffffffu, c[p], p);
        float rpv = __fdividef(1.0f, pv);
        float f = (i == p) ? 0.0f : c[p] * rpv;
        if (i == p) dinv = rpv;
        float ncp = (i == p) ? 1.0f : -f;
#pragma unroll
        for (int j = 0; j < N; j++)
            if (j != p) c[j] -= f * __shfl_sync(0xffffffffu, c[j], p);
        c[p] = ncp;
    }
    if (lane < N) {
#pragma unroll
        for (int j = 0; j < N; j++) M[i * LD + j] = c[j] * dinv;
    }
    __syncwarp();
}

// ---------------- Kernel A0: input projection for LSTM layer 0 ----------------
__global__ void xw0_kernel(const float* __restrict__ a,
                           const float* __restrict__ Wih0,
                           const float* __restrict__ bih0,
                           const float* __restrict__ bhh0) {
    int idx = blockIdx.x * blockDim.x + threadIdx.x;
    if (idx >= BSZ * TT * GG) return;
    int j  = idx % GG;
    int bt = idx / GG;
    const float* ar = a + (size_t)bt * DA;
    const float* w  = Wih0 + j * DA;
    float s = bih0[j] + bhh0[j];
#pragma unroll
    for (int d = 0; d < DA; d++) s += ar[d] * w[d];
    g_xw0[idx] = s;
}

// ---------------- Kernel A1: sequential 2-layer LSTM + softmax ----------------
__global__ void lstm_kernel(const float* __restrict__ Whh0,
                            const float* __restrict__ Wih1,
                            const float* __restrict__ Whh1,
                            const float* __restrict__ bih1,
                            const float* __restrict__ bhh1) {
    __shared__ float whh0[GG][3], wih1[GG][3], whh1[GG][3], b1[GG];
    int tid = threadIdx.x;
    if (tid < 36) {
        whh0[tid / 3][tid % 3] = Whh0[tid];
        wih1[tid / 3][tid % 3] = Wih1[tid];
        whh1[tid / 3][tid % 3] = Whh1[tid];
    }
    if (tid < GG) b1[tid] = bih1[tid] + bhh1[tid];
    __syncthreads();

    int b = tid;
    if (b >= BSZ) return;
    float h0[3] = {0, 0, 0}, c0[3] = {0, 0, 0};
    float h1[3] = {0, 0, 0}, c1[3] = {0, 0, 0};
    const float* xw = g_xw0 + (size_t)b * TT * GG;
    float* al = g_alpha + (size_t)b * TT * KK;

    for (int t = 0; t < TT; t++) {
        float g[GG];
#pragma unroll
        for (int j = 0; j < GG; j++)
            g[j] = xw[t * GG + j] + whh0[j][0] * h0[0] + whh0[j][1] * h0[1] + whh0[j][2] * h0[2];
#pragma unroll
        for (int u = 0; u < 3; u++) {
            c0[u] = fsigm(g[3 + u]) * c0[u] + fsigm(g[u]) * ftanh(g[6 + u]);
            h0[u] = fsigm(g[9 + u]) * ftanh(c0[u]);
        }
#pragma unroll
        for (int j = 0; j < GG; j++)
            g[j] = b1[j] + wih1[j][0] * h0[0] + wih1[j][1] * h0[1] + wih1[j][2] * h0[2]
                         + whh1[j][0] * h1[0] + whh1[j][1] * h1[1] + whh1[j][2] * h1[2];
#pragma unroll
        for (int u = 0; u < 3; u++) {
            c1[u] = fsigm(g[3 + u]) * c1[u] + fsigm(g[u]) * ftanh(g[6 + u]);
            h1[u] = fsigm(g[9 + u]) * ftanh(c1[u]);
        }
        float m = fmaxf(h1[0], fmaxf(h1[1], h1[2]));
        float e0 = __expf(h1[0] - m), e1 = __expf(h1[1] - m), e2 = __expf(h1[2] - m);
        float inv = __fdividef(1.0f, e0 + e1 + e2);
        al[t * KK + 0] = e0 * inv;
        al[t * KK + 1] = e1 * inv;
        al[t * KK + 2] = e2 * inv;
    }
}

// ---------------- Kernel B: forward Kalman filter ----------------
// Double-buffered At/Ct. Per step (4 barriers):
//   P1 issue-prefetch(regs) + r,M1,M1T | P2 S,WT,HT,w | P3 GJ16 (warp0) |
//   P45 Kg,G,V,updates + commit prefetch -> nxt buffers.
__global__ void __launch_bounds__(256) fwd_kernel(const float* __restrict__ a,
                                                  const float* __restrict__ A,
                                                  const float* __restrict__ C,
                                                  const float* __restrict__ R,
                                                  const float* __restrict__ Q,
                                                  const float* __restrict__ mu0,
                                                  const float* __restrict__ sigma0) {
    const int b = blockIdx.x;
    const int tid = threadIdx.x;
    const int i8 = tid >> 3;
    const int q4 = (tid & 7) * 4;
    const int jj = (tid & 7) * 2;

    __shared__ __align__(16) float sAt[2][DZ][36];
    __shared__ __align__(16) float sCt[2][DA][36];
    __shared__ __align__(16) float sCtT[2][DZ][20];
    __shared__ __align__(16) float sSigP[DZ][36], sQ[DZ][36];
    __shared__ __align__(16) float sWT[DZ][36];
    __shared__ __align__(16) float sM1[DZ][20], sKg[DZ][20], sG[DZ][20];
    __shared__ __align__(16) float sM1T[DA][36], sHT[DA][36];
    __shared__ __align__(16) float sS[DA][20];
    __shared__ float sR[DA][17];
    __shared__ float smu_f[DZ], smu_p[DZ], sw[DZ], sr[DA];

    float4 pA = make_float4(0, 0, 0, 0), pC = make_float4(0, 0, 0, 0);
    float pa = 0.f, pa2 = 0.f;

    if (tid < DZ) { smu_f[tid] = mu0[tid]; smu_p[tid] = mu0[tid]; }
    {
        int e = tid * 4, ii = e >> 5, jc = e & 31;
        *(float4*)&sSigP[ii][jc] = ((const float4*)sigma0)[tid];
        *(float4*)&sQ[ii][jc]    = ((const float4*)Q)[tid];
        sR[tid >> 4][tid & 15] = R[tid];
    }
    // prologue: mix t=0 into buffer 0
    {
        const size_t ab = (size_t)b * TT * KK;
        const float a0 = g_alpha[ab + 0], a1 = g_alpha[ab + 1], a2 = g_alpha[ab + 2];
        const float4* A0 = (const float4*)A;
        const float4* A1 = A0 + (size_t)TT * 256;
        const float4* A2 = A1 + (size_t)TT * 256;
        float4 v0 = A0[tid], v1 = A1[tid], v2 = A2[tid], m;
        m.x = a0 * v0.x + a1 * v1.x + a2 * v2.x;
        m.y = a0 * v0.y + a1 * v1.y + a2 * v2.y;
        m.z = a0 * v0.z + a1 * v1.z + a2 * v2.z;
        m.w = a0 * v0.w + a1 * v1.w + a2 * v2.w;
        int e = tid * 4, ii = e >> 5, jc = e & 31;
        *(float4*)&sAt[0][ii][jc] = m;
        if (tid < 128) {
            const float4* C0 = (const float4*)C;
            const float4* C1 = C0 + (size_t)TT * 128;
            const float4* C2 = C1 + (size_t)TT * 128;
            float4 w0 = C0[tid], w1 = C1[tid], w2 = C2[tid], c;
            c.x = a0 * w0.x + a1 * w1.x + a2 * w2.x;
            c.y = a0 * w0.y + a1 * w1.y + a2 * w2.y;
            c.z = a0 * w0.z + a1 * w1.z + a2 * w2.z;
            c.w = a0 * w0.w + a1 * w1.w + a2 * w2.w;
            int ec = tid * 4, ic = ec >> 5, jcc = ec & 31;
            *(float4*)&sCt[0][ic][jcc] = c;
            sCtT[0][jcc + 0][ic] = c.x; sCtT[0][jcc + 1][ic] = c.y;
            sCtT[0][jcc + 2][ic] = c.z; sCtT[0][jcc + 3][ic] = c.w;
        }
        if (tid < DA) pa = a[(size_t)b * TT * DA + tid];
    }
    __syncthreads();

    for (int t = 0; t < TT; t++) {
        const int cur = t & 1, nxt = cur ^ 1;

        // P1: issue prefetch (regs) for t+1 ; r = a - Ct mu_f ; M1 (+ M1T)
        if (t + 1 < TT) {
            const size_t ab2 = ((size_t)b * TT + (t + 1)) * KK;
            const float na0 = g_alpha[ab2 + 0];
            const float na1 = g_alpha[ab2 + 1];
            const float na2 = g_alpha[ab2 + 2];
            const float4* A0 = (const float4*)A + (size_t)(t + 1) * 256;
            const float4* A1 = A0 + (size_t)TT * 256;
            const float4* A2 = A1 + (size_t)TT * 256;
            float4 v0 = A0[tid], v1 = A1[tid], v2 = A2[tid];
            pA.x = na0 * v0.x + na1 * v1.x + na2 * v2.x;
            pA.y = na0 * v0.y + na1 * v1.y + na2 * v2.y;
            pA.z = na0 * v0.z + na1 * v1.z + na2 * v2.z;
            pA.w = na0 * v0.w + na1 * v1.w + na2 * v2.w;
            if (tid < 128) {
                const float4* C0 = (const float4*)C + (size_t)(t + 1) * 128;
                const float4* C1 = C0 + (size_t)TT * 128;
                const float4* C2 = C1 + (size_t)TT * 128;
                float4 w0 = C0[tid], w1 = C1[tid], w2 = C2[tid];
                pC.x = na0 * w0.x + na1 * w1.x + na2 * w2.x;
                pC.y = na0 * w0.y + na1 * w1.y + na2 * w2.y;
                pC.z = na0 * w0.z + na1 * w1.z + na2 * w2.z;
                pC.w = na0 * w0.w + na1 * w1.w + na2 * w2.w;
            }
            if (tid < DA) pa2 = a[((size_t)b * TT + (t + 1)) * DA + tid];
        }
        if (tid < DA) {
            float s = pa;
#pragma unroll
            for (int j = 0; j < DZ; j++) s -= sCt[cur][tid][j] * smu_f[j];
            sr[tid] = s;
        }
        {
            float s0 = 0.f, s1 = 0.f;
#pragma unroll
            for (int k = 0; k < DZ; k++) {
                float av = sSigP[i8][k];
                s0 += av * sCtT[cur][k][jj];
                s1 += av * sCtT[cur][k][jj + 1];
            }
            sM1[i8][jj] = s0; sM1[i8][jj + 1] = s1;
            sM1T[jj][i8] = s0; sM1T[jj + 1][i8] = s1;
        }
        __syncthreads();

        // P2: S = Ct*M1 + R ; WT = (At*sigP)^T ; HT = (At*M1)^T ; w = At*mu_p
        {
            {
                int i = tid >> 4, j = tid & 15;
                float s = sR[i][j];
#pragma unroll
                for (int k = 0; k < DZ; k++) s += sCt[cur][i][k] * sM1[k][j];
                sS[i][j] = s;
            }
            {
                float4 acc = make_float4(0, 0, 0, 0);
#pragma unroll
                for (int k = 0; k < DZ; k++) {
                    float av = sAt[cur][i8][k];
                    float4 bv = *(const float4*)&sSigP[k][q4];
                    acc.x += av * bv.x; acc.y += av * bv.y;
                    acc.z += av * bv.z; acc.w += av * bv.w;
                }
                sWT[q4 + 0][i8] = acc.x; sWT[q4 + 1][i8] = acc.y;
                sWT[q4 + 2][i8] = acc.z; sWT[q4 + 3][i8] = acc.w;
            }
#pragma unroll
            for (int rep = 0; rep < 2; rep++) {
                int u = tid + rep * 256;
                int i = u >> 4, j = u & 15;
                float h = 0.f;
#pragma unroll
                for (int k = 0; k < DZ; k++) h += sAt[cur][i][k] * sM1[k][j];
                sHT[j][i] = h;
            }
            if (tid < DZ) {
                float s = 0.f;
#pragma unroll
                for (int k = 0; k < DZ; k++) s += sAt[cur][tid][k] * smu_p[k];
                sw[tid] = s;
            }
        }
        __syncthreads();

        // P3: warp 0 inverts S in place (serial)
        if (tid < 32) warp_gj_reg<DA, 20>(&sS[0][0], tid);
        __syncthreads();

        // P45: Kg,G,V,updates ; commit prefetched mix into nxt buffers
        {
            float k0 = 0.f, k1 = 0.f, g0 = 0.f, g1 = 0.f;
#pragma unroll
            for (int k = 0; k < DA; k++) {
                float m = sM1[i8][k];
                float h = sHT[k][i8];
                float s0 = sS[k][jj], s1 = sS[k][jj + 1];
                k0 += m * s0; k1 += m * s1;
                g0 += h * s0; g1 += h * s1;
            }
            sKg[i8][jj] = k0; sKg[i8][jj + 1] = k1;
            sG[i8][jj]  = g0; sG[i8][jj + 1]  = g1;
            __syncwarp();

            const size_t sb = (size_t)t * BSZ + b;

            float4 accN = *(const float4*)&sSigP[i8][q4];
            float4 accP = *(const float4*)&sQ[i8][q4];
#pragma unroll
            for (int k = 0; k < DZ; k++) {
                float av = sAt[cur][i8][k];
                float4 bv = *(const float4*)&sWT[k][q4];
                accP.x += av * bv.x; accP.y += av * bv.y;
                accP.z += av * bv.z; accP.w += av * bv.w;
            }
#pragma unroll
            for (int k = 0; k < DA; k++) {
                float kg = sKg[i8][k];
                float gg = sG[i8][k];
                float4 m = *(const float4*)&sM1T[k][q4];
                float4 h = *(const float4*)&sHT[k][q4];
                accN.x -= kg * m.x; accN.y -= kg * m.y;
                accN.z -= kg * m.z; accN.w -= kg * m.w;
                accP.x -= gg * h.x; accP.y -= gg * h.y;
                accP.z -= gg * h.z; accP.w -= gg * h.w;
            }
            *(float4*)&g_sigf[sb * (DZ * DZ) + i8 * DZ + q4] = accN;
            *(float4*)&sSigP[i8][q4] = accP;
            *(float4*)&g_sigp[sb * (DZ * DZ) + i8 * DZ + q4] = accP;

            float pm = k0 * sr[jj] + k1 * sr[jj + 1];
            float pg = g0 * sr[jj] + g1 * sr[jj + 1];
#pragma unroll
            for (int o = 4; o >= 1; o >>= 1) {
                pm += __shfl_down_sync(0xffffffffu, pm, o);
                pg += __shfl_down_sync(0xffffffffu, pg, o);
            }
            if ((tid & 7) == 0) {
                float mn = smu_p[i8] + pm;
                float mp = sw[i8] + pg;
                smu_f[i8] = mn; g_muf[sb * DZ + i8] = mn;
                smu_p[i8] = mp; g_mup[sb * DZ + i8] = mp;
            }

            // commit prefetch (loads issued at P1 top; long since landed)
            if (t + 1 < TT) {
                int e = tid * 4, ii = e >> 5, jc = e & 31;
                *(float4*)&sAt[nxt][ii][jc] = pA;
                if (tid < 128) {
                    int ec = tid * 4, ic = ec >> 5, jcc = ec & 31;
                    *(float4*)&sCt[nxt][ic][jcc] = pC;
                    sCtT[nxt][jcc + 0][ic] = pC.x; sCtT[nxt][jcc + 1][ic] = pC.y;
                    sCtT[nxt][jcc + 2][ic] = pC.z; sCtT[nxt][jcc + 3][ic] = pC.w;
                }
                pa = pa2;
            }
        }
        __syncthreads();
    }
}

// ---------------- Kernel I: batch-parallel inversion of all sigp_t ----------
__global__ void __launch_bounds__(256) inv_kernel() {
    const int w = blockIdx.x * (blockDim.x >> 5) + (threadIdx.x >> 5);
    if (w >= TT * BSZ) return;
    const int lane = threadIdx.x & 31;

    const float4* src = (const float4*)(g_sigp + (size_t)w * (DZ * DZ));
    float c[DZ];
#pragma unroll
    for (int s = 0; s < 8; s++) {
        float4 v = src[lane * 8 + s];
        c[s * 4 + 0] = v.x; c[s * 4 + 1] = v.y;
        c[s * 4 + 2] = v.z; c[s * 4 + 3] = v.w;
    }
    float dinv = 1.0f;
#pragma unroll
    for (int p = 0; p < DZ; p++) {
        float pv = __shfl_sync(0xffffffffu, c[p], p);
        float rpv = __fdividef(1.0f, pv);
        float f = (lane == p) ? 0.0f : c[p] * rpv;
        if (lane == p) dinv = rpv;
        float ncp = (lane == p) ? 1.0f : -f;
#pragma unroll
        for (int j = 0; j < DZ; j++)
            if (j != p) c[j] -= f * __shfl_sync(0xffffffffu, c[j], p);
        c[p] = ncp;
    }
    float4* dst = (float4*)(g_pinv + (size_t)w * (DZ * DZ));
#pragma unroll
    for (int s = 0; s < 8; s++) {
        float4 v;
        v.x = c[s * 4 + 0] * dinv; v.y = c[s * 4 + 1] * dinv;
        v.z = c[s * 4 + 2] * dinv; v.w = c[s * 4 + 3] * dinv;
        dst[lane * 8 + s] = v;
    }
}

// ---------------- Kernel C: RTS backward smoother (2 barriers/step) ----------
// P1 prefetch-issue + U,X,xv | P2 outputs + commit prefetched inputs.
__global__ void __launch_bounds__(256) bwd_kernel(const float* __restrict__ A,
                                                  float* __restrict__ out) {
    const int b = blockIdx.x;
    const int tid = threadIdx.x;
    const int i8 = tid >> 3;
    const int q4 = (tid & 7) * 4;

    __shared__ __align__(16) float sAT[DZ][36];
    __shared__ __align__(16) float sSigF[2][DZ][36];
    __shared__ __align__(16) float sSigNc[DZ][36], sD[DZ][36];
    __shared__ __align__(16) float sU[DZ][36], sX[DZ][36], sPinv[DZ][36];
    __shared__ float sMuN[DZ], sMuD[DZ], sxv[DZ];

    float4 pAT = make_float4(0, 0, 0, 0);
    float4 pSF = make_float4(0, 0, 0, 0);
    float4 pPI = make_float4(0, 0, 0, 0);
    float4 pSP = make_float4(0, 0, 0, 0);
    float pMUP = 0.f;

    // prologue: t = TT-1 outputs + carry ; load t = TT-2 inputs into buffers[0]
    {
        size_t sb = ((size_t)(TT - 1) * BSZ + b);
        size_t ob = ((size_t)b * TT + (TT - 1)) * (DZ + DZ * DZ);
        int e = tid * 4, ii = e >> 5, jj = e & 31;
        float4 v = ((const float4*)(g_sigf + sb * (DZ * DZ)))[tid];
        *(float4*)&sSigNc[ii][jj] = v;
        *(float4*)&out[ob + DZ + e] = v;
        if (tid < DZ) {
            float m = g_muf[sb * DZ + tid];
            sMuN[tid] = m;
            out[ob + tid] = m;
        }
        const int t0 = TT - 2;
        const size_t sb2 = (size_t)t0 * BSZ + b;
        const size_t ab = ((size_t)b * TT + (t0 + 1)) * KK;
        const float a0 = g_alpha[ab + 0], a1 = g_alpha[ab + 1], a2 = g_alpha[ab + 2];
        const float4* A0 = (const float4*)A + (size_t)(t0 + 1) * 256;
        const float4* A1 = A0 + (size_t)TT * 256;
        const float4* A2 = A1 + (size_t)TT * 256;
        float4 v0 = A0[tid], v1 = A1[tid], v2 = A2[tid];
        sAT[jj + 0][ii] = a0 * v0.x + a1 * v1.x + a2 * v2.x;
        sAT[jj + 1][ii] = a0 * v0.y + a1 * v1.y + a2 * v2.y;
        sAT[jj + 2][ii] = a0 * v0.z + a1 * v1.z + a2 * v2.z;
        sAT[jj + 3][ii] = a0 * v0.w + a1 * v1.w + a2 * v2.w;
        *(float4*)&sSigF[0][ii][jj] = ((const float4*)(g_sigf + sb2 * (DZ * DZ)))[tid];
        *(float4*)&sPinv[ii][jj] = ((const float4*)(g_pinv + sb2 * (DZ * DZ)))[tid];
        float4 sp = ((const float4*)(g_sigp + sb2 * (DZ * DZ)))[tid];
        float4 n = make_float4(sSigNc[ii][jj + 0], sSigNc[ii][jj + 1],
                               sSigNc[ii][jj + 2], sSigNc[ii][jj + 3]);
        float4 d = make_float4(n.x - sp.x, n.y - sp.y, n.z - sp.z, n.w - sp.w);
        *(float4*)&sD[ii][jj] = d;
        if (tid < DZ) sMuD[tid] = sMuN[tid] - g_mup[sb2 * DZ + tid];
    }
    __syncthreads();

    for (int t = TT - 2; t >= 0; t--) {
        const int cur = (TT - 2 - t) & 1, nxt = cur ^ 1;
        const size_t sb = (size_t)t * BSZ + b;

        // P1: issue prefetch for t-1 ; compute U = sigF*AT, X = Pinv*D, xv
        if (t > 0) {
            const int t2 = t - 1;
            const size_t sb2 = (size_t)t2 * BSZ + b;
            const size_t ab2 = ((size_t)b * TT + (t2 + 1)) * KK;
            const float na0 = g_alpha[ab2 + 0];
            const float na1 = g_alpha[ab2 + 1];
            const float na2 = g_alpha[ab2 + 2];
            const float4* A0 = (const float4*)A + (size_t)(t2 + 1) * 256;
            const float4* A1 = A0 + (size_t)TT * 256;
            const float4* A2 = A1 + (size_t)TT * 256;
            float4 v0 = A0[tid], v1 = A1[tid], v2 = A2[tid];
            pAT.x = na0 * v0.x + na1 * v1.x + na2 * v2.x;
            pAT.y = na0 * v0.y + na1 * v1.y + na2 * v2.y;
            pAT.z = na0 * v0.z + na1 * v1.z + na2 * v2.z;
            pAT.w = na0 * v0.w + na1 * v1.w + na2 * v2.w;
            pSF = ((const float4*)(g_sigf + sb2 * (DZ * DZ)))[tid];
            pPI = ((const float4*)(g_pinv + sb2 * (DZ * DZ)))[tid];
            pSP = ((const float4*)(g_sigp + sb2 * (DZ * DZ)))[tid];
            if (tid < DZ) pMUP = g_mup[sb2 * DZ + tid];
        }
        {
            float4 au = make_float4(0, 0, 0, 0);
            float4 ax = make_float4(0, 0, 0, 0);
#pragma unroll
            for (int k = 0; k < DZ; k++) {
                float fu = sSigF[cur][i8][k];
                float fx = sPinv[i8][k];
                float4 bu = *(const float4*)&sAT[k][q4];
                float4 bx = *(const float4*)&sD[k][q4];
                au.x += fu * bu.x; au.y += fu * bu.y;
                au.z += fu * bu.z; au.w += fu * bu.w;
                ax.x += fx * bx.x; ax.y += fx * bx.y;
                ax.z += fx * bx.z; ax.w += fx * bx.w;
            }
            *(float4*)&sU[i8][q4] = au;
            *(float4*)&sX[i8][q4] = ax;
            if (tid < DZ) {
                float s = 0.f;
#pragma unroll
                for (int k = 0; k < DZ; k++) s += sPinv[tid][k] * sMuD[k];
                sxv[tid] = s;
            }
        }
        __syncthreads();

        // P2: outputs + carry ; commit prefetched inputs
        {
            const size_t ob = ((size_t)b * TT + t) * (DZ + DZ * DZ);
            float4 acc = *(const float4*)&sSigF[cur][i8][q4];
#pragma unroll
            for (int k = 0; k < DZ; k++) {
                float av = sU[i8][k];
                float4 bv = *(const float4*)&sX[k][q4];
                acc.x += av * bv.x; acc.y += av * bv.y;
                acc.z += av * bv.z; acc.w += av * bv.w;
            }
            *(float4*)&sSigNc[i8][q4] = acc;
            *(float4*)&out[ob + DZ + i8 * DZ + q4] = acc;
            float muNew = 0.f;
            if (tid < DZ) {
                float s = g_muf[sb * DZ + tid];
#pragma unroll
                for (int k = 0; k < DZ; k++) s += sU[tid][k] * sxv[k];
                muNew = s;
                sMuN[tid] = s;
                out[ob + tid] = s;
            }
            if (t > 0) {
                int e = tid * 4, ii = e >> 5, jj = e & 31;
                sAT[jj + 0][ii] = pAT.x; sAT[jj + 1][ii] = pAT.y;
                sAT[jj + 2][ii] = pAT.z; sAT[jj + 3][ii] = pAT.w;
                *(float4*)&sSigF[nxt][ii][jj] = pSF;
                *(float4*)&sPinv[ii][jj] = pPI;
                float4 d = make_float4(acc.x - pSP.x, acc.y - pSP.y,
                                       acc.z - pSP.z, acc.w - pSP.w);
                *(float4*)&sD[ii][jj] = d;
                if (tid < DZ) sMuD[tid] = muNew - pMUP;
            }
        }
        __syncthreads();
    }
}

// ---------------- launch ----------------
extern "C" void kernel_launch(void* const* d_in, const int* in_sizes, int n_in,
                              void* d_out, int out_size) {
    const float* a      = (const float*)d_in[0];
    const float* A      = (const float*)d_in[1];
    const float* C      = (const float*)d_in[2];
    const float* R      = (const float*)d_in[3];
    const float* Q      = (const float*)d_in[4];
    const float* mu0    = (const float*)d_in[5];
    const float* sigma0 = (const float*)d_in[6];
    const float* Wih0   = (const float*)d_in[7];
    const float* Whh0   = (const float*)d_in[8];
    const float* bih0   = (const float*)d_in[9];
    const float* bhh0   = (const float*)d_in[10];
    const float* Wih1   = (const float*)d_in[11];
    const float* Whh1   = (const float*)d_in[12];
    const float* bih1   = (const float*)d_in[13];
    const float* bhh1   = (const float*)d_in[14];
    float* out = (float*)d_out;

    int n0 = BSZ * TT * GG;
    xw0_kernel<<<(n0 + 255) / 256, 256>>>(a, Wih0, bih0, bhh0);
    lstm_kernel<<<1, 64>>>(Whh0, Wih1, Whh1, bih1, bhh1);
    fwd_kernel<<<BSZ, 256>>>(a, A, C, R, Q, mu0, sigma0);
    inv_kernel<<<(TT * BSZ) / 8, 256>>>();
    bwd_kernel<<<BSZ, 256>>>(A, out);
}